// round 6
// baseline (speedup 1.0000x reference)
#include <cuda_runtime.h>

// KernelRepeatLinear: out[b,e,j] = bias[j] + sum_k weight[k,j] * P[b, e-7+k, j]
// P[b,e,j] = sum_{i<=j} x[b,e,i] * dv^(j-i)   (decayed inclusive prefix scan over dim)
#define Bv 8
#define Ev 2048
#define Sv 512
#define Kv 8
#define HALO (Kv - 1)
#define TE 8                  // output E-rows per block (small tile -> high occupancy)
#define ROWS (TE + HALO)      // 15 scanned rows per block
#define THREADS 256

// packed fp32x2 FMA (Blackwell)
#define FMA_F32X2(d, a, b, c) \
    asm("fma.rn.f32x2 %0, %1, %2, %3;" : "=l"(d) : "l"(a), "l"(b), "l"(c))

__global__ __launch_bounds__(THREADS, 4)   // force <=64 regs -> 4 CTAs/SM
void krl_fused6(const float* __restrict__ x,
                const float* __restrict__ weight,
                const float* __restrict__ bias,
                const float* __restrict__ decay,
                float* __restrict__ out)
{
    __shared__ float shP[ROWS * Sv];   // 30720 B

    const int tid  = threadIdx.x;
    const int lane = tid & 31;
    const int warp = tid >> 5;         // 0..7

    const int blocksPerBatch = Ev / TE;           // 256
    const int b  = blockIdx.x / blocksPerBatch;
    const int t  = blockIdx.x % blocksPerBatch;
    const int e0 = t * TE;

    float dv = decay[1];
    dv = fminf(1.0f, fmaxf(0.9f, dv));

    // dv^1..dv^4 (group powers); dv16 = (dv^4)^4 (warp-scan hop factor)
    const float dv2 = dv * dv;
    const float dv3 = dv2 * dv;
    const float dv4 = dv2 * dv2;
    const float dv8 = dv4 * dv4;
    const float dv16 = dv8 * dv8;

    const float* xb = x + (size_t)b * Ev * Sv;

    // -------- Phase 1: decayed prefix scan; warp w does rows w and w+8 --------
    #pragma unroll
    for (int it = 0; it < 2; ++it) {
        const int r = warp + it * 8;
        if (r >= ROWS) break;                     // only warp 7, it=1
        const int g = e0 - HALO + r;              // global E-row
        float4* dst = (float4*)(shP + r * Sv);

        float4 a[4];
        if (g >= 0) {
            const float4* src = (const float4*)(xb + (size_t)g * Sv);
            #pragma unroll
            for (int q = 0; q < 4; ++q) a[q] = src[4 * lane + q];
        } else {                                   // halo before sequence start
            #pragma unroll
            for (int q = 0; q < 4; ++q) a[q] = make_float4(0.f, 0.f, 0.f, 0.f);
        }

        // serial scan of this lane's 16 elems (zero incoming carry)
        float p = 0.f;
        #pragma unroll
        for (int q = 0; q < 4; ++q) {
            p = fmaf(dv, p, a[q].x); a[q].x = p;
            p = fmaf(dv, p, a[q].y); a[q].y = p;
            p = fmaf(dv, p, a[q].z); a[q].z = p;
            p = fmaf(dv, p, a[q].w); a[q].w = p;
        }
        // Kogge-Stone inclusive warp scan of segment ends, hop factor dv^(16*d)
        float s = p;
        float f = dv16;
        #pragma unroll
        for (int d = 1; d < 32; d <<= 1) {
            float o = __shfl_up_sync(0xffffffffu, s, d);
            if (lane >= d) s = fmaf(f, o, s);
            f = f * f;
        }
        float carry = __shfl_up_sync(0xffffffffu, s, 1);
        if (lane == 0) carry = 0.f;

        // apply carry: group chain c_q = carry*dv^(4q+1); in-group independent
        float cq = carry * dv;                     // carry * dv^(4q+1), q=0
        #pragma unroll
        for (int q = 0; q < 4; ++q) {
            a[q].x = fmaf(cq, 1.0f, a[q].x);       // + cq*dv^0
            a[q].y = fmaf(cq, dv,   a[q].y);
            a[q].z = fmaf(cq, dv2,  a[q].z);
            a[q].w = fmaf(cq, dv3,  a[q].w);
            dst[4 * lane + q] = a[q];
            cq = cq * dv4;
        }
    }

    // hoist weight/bias loads above the barrier: LDG latency hides in bar wait
    const int jq = tid;                            // float2 column, 0..255
    unsigned long long wv[Kv];
    #pragma unroll
    for (int k = 0; k < Kv; ++k)
        wv[k] = ((const unsigned long long*)(weight + k * Sv))[jq];
    const unsigned long long bv = ((const unsigned long long*)bias)[jq];

    __syncthreads();

    // -------- Phase 2: 8-tap FIR over E; thread owns one float2 column --------
    unsigned long long win[8];
    #pragma unroll
    for (int i = 0; i < HALO; ++i)
        win[i] = ((const unsigned long long*)(shP + i * Sv))[jq];

    unsigned long long* outp =
        (unsigned long long*)(out + ((size_t)b * Ev + e0) * Sv);

    #pragma unroll
    for (int s = 0; s < TE; ++s) {
        win[(s + HALO) & 7] = ((const unsigned long long*)(shP + (s + HALO) * Sv))[jq];
        unsigned long long acc = bv;
        #pragma unroll
        for (int k = 0; k < Kv; ++k)
            FMA_F32X2(acc, wv[k], win[(s + k) & 7], acc);
        outp[(size_t)s * (Sv / 2) + jq] = acc;
    }
}

extern "C" void kernel_launch(void* const* d_in, const int* in_sizes, int n_in,
                              void* d_out, int out_size)
{
    const float* x      = (const float*)d_in[0];  // (B, E, S)
    const float* weight = (const float*)d_in[1];  // (K, S)
    const float* bias   = (const float*)d_in[2];  // (S,)
    const float* decay  = (const float*)d_in[3];  // (2, 1)
    float* out          = (float*)d_out;          // (B, E, S)

    krl_fused6<<<Bv * (Ev / TE), THREADS>>>(x, weight, bias, decay, out);
}

// round 7
// speedup vs baseline: 1.1174x; 1.1174x over previous
#include <cuda_runtime.h>

// KernelRepeatLinear: out[b,e,j] = bias[j] + sum_k weight[k,j] * P[b, e-7+k, j]
// P[b,e,j] = sum_{i<=j} x[b,e,i] * dv^(j-i)   (decayed inclusive prefix scan over dim)
#define Bv 8
#define Ev 2048
#define Sv 512
#define Kv 8
#define HALO (Kv - 1)
#define TE 16                 // output E-rows per block
#define ROWS (TE + HALO)      // 23 scanned rows
#define THREADS 512

// packed fp32x2 FMA (Blackwell)
#define FMA_F32X2(d, a, b, c) \
    asm("fma.rn.f32x2 %0, %1, %2, %3;" : "=l"(d) : "l"(a), "l"(b), "l"(c))

__global__ __launch_bounds__(THREADS, 2)
void krl_fused7(const float* __restrict__ x,
                const float* __restrict__ weight,
                const float* __restrict__ bias,
                const float* __restrict__ decay,
                float* __restrict__ out)
{
    __shared__ float shP[ROWS * Sv];   // 47104 B

    const int tid  = threadIdx.x;
    const int lane = tid & 31;
    const int warp = tid >> 5;         // 0..15

    const int blocksPerBatch = Ev / TE;           // 128
    const int b  = blockIdx.x / blocksPerBatch;
    const int t  = blockIdx.x % blocksPerBatch;
    const int e0 = t * TE;

    float dv = decay[1];
    dv = fminf(1.0f, fmaxf(0.9f, dv));

    // group powers; dv16 = warp-scan hop factor
    const float dv2 = dv * dv;
    const float dv3 = dv2 * dv;
    const float dv4 = dv2 * dv2;
    const float dv8 = dv4 * dv4;
    const float dv16 = dv8 * dv8;

    const float* xb = x + (size_t)b * Ev * Sv;

    // -------- Phase 1: decayed prefix scan; warp w does rows w and w+16 --------
    #pragma unroll
    for (int it = 0; it < 2; ++it) {
        const int r = warp + it * 16;
        if (r >= ROWS) break;                     // it=1 only for warps 0..6
        const int g = e0 - HALO + r;              // global E-row
        float4* dst = (float4*)(shP + r * Sv);

        float4 a[4];
        if (g >= 0) {
            const float4* src = (const float4*)(xb + (size_t)g * Sv);
            #pragma unroll
            for (int q = 0; q < 4; ++q) a[q] = src[4 * lane + q];
        } else {                                   // halo before sequence start
            #pragma unroll
            for (int q = 0; q < 4; ++q) a[q] = make_float4(0.f, 0.f, 0.f, 0.f);
        }

        // serial scan of this lane's 16 elems (zero incoming carry)
        float p = 0.f;
        #pragma unroll
        for (int q = 0; q < 4; ++q) {
            p = fmaf(dv, p, a[q].x); a[q].x = p;
            p = fmaf(dv, p, a[q].y); a[q].y = p;
            p = fmaf(dv, p, a[q].z); a[q].z = p;
            p = fmaf(dv, p, a[q].w); a[q].w = p;
        }
        // Kogge-Stone inclusive warp scan of segment ends, hop factor dv^(16*d)
        float s = p;
        float f = dv16;
        #pragma unroll
        for (int d = 1; d < 32; d <<= 1) {
            float o = __shfl_up_sync(0xffffffffu, s, d);
            if (lane >= d) s = fmaf(f, o, s);
            f = f * f;
        }
        float carry = __shfl_up_sync(0xffffffffu, s, 1);
        if (lane == 0) carry = 0.f;

        // apply carry: per-group scalar cq = carry*dv^(4q+1); in-group independent
        float cq = carry * dv;
        #pragma unroll
        for (int q = 0; q < 4; ++q) {
            a[q].x = a[q].x + cq;                  // + cq*dv^0
            a[q].y = fmaf(cq, dv,  a[q].y);
            a[q].z = fmaf(cq, dv2, a[q].z);
            a[q].w = fmaf(cq, dv3, a[q].w);
            dst[4 * lane + q] = a[q];
            cq = cq * dv4;
        }
    }

    // hoist weight/bias loads above the barrier: LDG latency hides in bar wait
    const int jq  = tid & 255;                     // float2 column, 0..255
    const int grp = tid >> 8;                      // 0 or 1
    const int rb  = grp * 8;                       // first output row of group

    unsigned long long wv[Kv];
    #pragma unroll
    for (int k = 0; k < Kv; ++k)
        wv[k] = ((const unsigned long long*)(weight + k * Sv))[jq];
    const unsigned long long bv = ((const unsigned long long*)bias)[jq];

    __syncthreads();

    // -------- Phase 2: 8-tap FIR; 256 f2-columns x 2 groups of 8 output rows --
    unsigned long long win[8];
    #pragma unroll
    for (int i = 0; i < HALO; ++i)
        win[i] = ((const unsigned long long*)(shP + (rb + i) * Sv))[jq];

    unsigned long long* outp =
        (unsigned long long*)(out + ((size_t)b * Ev + e0 + rb) * Sv);

    #pragma unroll
    for (int s = 0; s < 8; ++s) {
        win[(s + HALO) & 7] =
            ((const unsigned long long*)(shP + (rb + s + HALO) * Sv))[jq];
        unsigned long long acc = bv;
        #pragma unroll
        for (int k = 0; k < Kv; ++k)
            FMA_F32X2(acc, wv[k], win[(s + k) & 7], acc);
        outp[(size_t)s * (Sv / 2) + jq] = acc;
    }
}

extern "C" void kernel_launch(void* const* d_in, const int* in_sizes, int n_in,
                              void* d_out, int out_size)
{
    const float* x      = (const float*)d_in[0];  // (B, E, S)
    const float* weight = (const float*)d_in[1];  // (K, S)
    const float* bias   = (const float*)d_in[2];  // (S,)
    const float* decay  = (const float*)d_in[3];  // (2, 1)
    float* out          = (float*)d_out;          // (B, E, S)

    krl_fused7<<<Bv * (Ev / TE), THREADS>>>(x, weight, bias, decay, out);
}

// round 8
// speedup vs baseline: 1.2061x; 1.0794x over previous
#include <cuda_runtime.h>
#include <cstdint>

// KernelRepeatLinear: out[b,e,j] = bias[j] + sum_k weight[k,j] * P[b, e-7+k, j]
// P[b,e,j] = sum_{i<=j} x[b,e,i] * dv^(j-i)   (decayed inclusive prefix scan over dim)
#define Bv 8
#define Ev 2048
#define Sv 512
#define Kv 8
#define HALO (Kv - 1)
#define TE 16                 // output E-rows per block
#define ROWS (TE + HALO)      // 23 scanned rows (contiguous in gmem!)
#define THREADS 256

// packed fp32x2 FMA (Blackwell)
#define FMA_F32X2(d, a, b, c) \
    asm("fma.rn.f32x2 %0, %1, %2, %3;" : "=l"(d) : "l"(a), "l"(b), "l"(c))

__global__ __launch_bounds__(THREADS, 4)
void krl_fused8(const float* __restrict__ x,
                const float* __restrict__ weight,
                const float* __restrict__ bias,
                const float* __restrict__ decay,
                float* __restrict__ out)
{
    __shared__ float shP[ROWS * Sv];                 // 47104 B tile (x, then P in place)
    __shared__ __align__(8) unsigned long long mbar; // TMA completion barrier

    const int tid  = threadIdx.x;
    const int lane = tid & 31;
    const int warp = tid >> 5;         // 0..7

    const int blocksPerBatch = Ev / TE;           // 128
    const int b  = blockIdx.x / blocksPerBatch;
    const int t  = blockIdx.x % blocksPerBatch;
    const int e0 = t * TE;

    const float* xb = x + (size_t)b * Ev * Sv;

    uint32_t mbar_addr;
    {
        uint64_t tmp;
        asm("cvta.to.shared.u64 %0, %1;" : "=l"(tmp) : "l"(&mbar));
        mbar_addr = (uint32_t)tmp;
    }
    uint32_t shP_addr;
    {
        uint64_t tmp;
        asm("cvta.to.shared.u64 %0, %1;" : "=l"(tmp) : "l"(shP));
        shP_addr = (uint32_t)tmp;
    }

    // ---- init barrier, then one thread kicks off the whole-tile bulk copy ----
    if (tid == 0)
        asm volatile("mbarrier.init.shared.b64 [%0], %1;" :: "r"(mbar_addr), "r"(1) : "memory");
    __syncthreads();

    const int gFirstWanted = e0 - HALO;                 // may be <0 on first tile
    const int gFirst       = gFirstWanted < 0 ? 0 : gFirstWanted;
    const int dstRow       = gFirst - gFirstWanted;     // 0, or 7 when t==0
    const int nRows        = (e0 + TE) - gFirst;        // 23, or 16 when t==0
    const uint32_t bytes   = (uint32_t)nRows * Sv * 4u;

    if (tid == 0) {
        asm volatile("mbarrier.arrive.expect_tx.shared.b64 _, [%0], %1;"
                     :: "r"(mbar_addr), "r"(bytes) : "memory");
        asm volatile("cp.async.bulk.shared::cta.global.mbarrier::complete_tx::bytes "
                     "[%0], [%1], %2, [%3];"
                     :: "r"(shP_addr + (uint32_t)dstRow * Sv * 4u),
                        "l"(xb + (size_t)gFirst * Sv),
                        "r"(bytes), "r"(mbar_addr) : "memory");
    }

    // zero halo rows (only first tile of a batch) — disjoint from TMA dst
    if (dstRow != 0) {
        float4* z = (float4*)shP;
        for (int i = tid; i < dstRow * (Sv / 4); i += THREADS)
            z[i] = make_float4(0.f, 0.f, 0.f, 0.f);
    }

    float dv = decay[1];
    dv = fminf(1.0f, fmaxf(0.9f, dv));
    const float dv2 = dv * dv;
    const float dv3 = dv2 * dv;
    const float dv4 = dv2 * dv2;
    const float dv8 = dv4 * dv4;
    const float dv16 = dv8 * dv8;

    // hoist weight/bias LDGs: latency hides behind the TMA wait
    const int jq = tid;                            // float2 column, 0..255
    unsigned long long wv[Kv];
    #pragma unroll
    for (int k = 0; k < Kv; ++k)
        wv[k] = ((const unsigned long long*)(weight + k * Sv))[jq];
    const unsigned long long bv = ((const unsigned long long*)bias)[jq];

    // ---- wait for the TMA tile (acquire orders subsequent LDS) ----
    {
        uint32_t done;
        asm volatile(
            "{\n\t.reg .pred p;\n\t"
            "mbarrier.try_wait.parity.acquire.cta.shared::cta.b64 p, [%1], %2;\n\t"
            "selp.b32 %0, 1, 0, p;\n\t}"
            : "=r"(done) : "r"(mbar_addr), "r"(0) : "memory");
        if (!done) {
            asm volatile(
                "{\n\t.reg .pred P1;\n\t"
                "WAIT_LOOP_%=:\n\t"
                "mbarrier.try_wait.parity.acquire.cta.shared::cta.b64 P1, [%0], %1, 0x989680;\n\t"
                "@P1 bra.uni WAIT_DONE_%=;\n\t"
                "bra.uni WAIT_LOOP_%=;\n\t"
                "WAIT_DONE_%=:\n\t}"
                :: "r"(mbar_addr), "r"(0) : "memory");
        }
    }
    __syncthreads();   // zeros visible + everyone past the wait

    // -------- Phase 1: in-place decayed prefix scan (LDS -> regs -> STS) ------
    for (int r = warp; r < ROWS; r += 8) {
        float4* rowp = (float4*)(shP + r * Sv);
        float4 a[4];
        #pragma unroll
        for (int q = 0; q < 4; ++q) a[q] = rowp[4 * lane + q];

        float p = 0.f;
        #pragma unroll
        for (int q = 0; q < 4; ++q) {
            p = fmaf(dv, p, a[q].x); a[q].x = p;
            p = fmaf(dv, p, a[q].y); a[q].y = p;
            p = fmaf(dv, p, a[q].z); a[q].z = p;
            p = fmaf(dv, p, a[q].w); a[q].w = p;
        }
        float s = p;
        float f = dv16;
        #pragma unroll
        for (int d = 1; d < 32; d <<= 1) {
            float o = __shfl_up_sync(0xffffffffu, s, d);
            if (lane >= d) s = fmaf(f, o, s);
            f = f * f;
        }
        float carry = __shfl_up_sync(0xffffffffu, s, 1);
        if (lane == 0) carry = 0.f;

        float cq = carry * dv;                     // carry * dv^(4q+1)
        #pragma unroll
        for (int q = 0; q < 4; ++q) {
            a[q].x = a[q].x + cq;
            a[q].y = fmaf(cq, dv,  a[q].y);
            a[q].z = fmaf(cq, dv2, a[q].z);
            a[q].w = fmaf(cq, dv3, a[q].w);
            rowp[4 * lane + q] = a[q];
            cq = cq * dv4;
        }
    }
    __syncthreads();

    // -------- Phase 2: 8-tap FIR over E; thread owns one float2 column --------
    unsigned long long win[8];
    #pragma unroll
    for (int i = 0; i < HALO; ++i)
        win[i] = ((const unsigned long long*)(shP + i * Sv))[jq];

    unsigned long long* outp =
        (unsigned long long*)(out + ((size_t)b * Ev + e0) * Sv);

    #pragma unroll
    for (int s = 0; s < TE; ++s) {
        win[(s + HALO) & 7] = ((const unsigned long long*)(shP + (s + HALO) * Sv))[jq];
        unsigned long long acc = bv;
        #pragma unroll
        for (int k = 0; k < Kv; ++k)
            FMA_F32X2(acc, wv[k], win[(s + k) & 7], acc);
        outp[(size_t)s * (Sv / 2) + jq] = acc;
    }
}

extern "C" void kernel_launch(void* const* d_in, const int* in_sizes, int n_in,
                              void* d_out, int out_size)
{
    const float* x      = (const float*)d_in[0];  // (B, E, S)
    const float* weight = (const float*)d_in[1];  // (K, S)
    const float* bias   = (const float*)d_in[2];  // (S,)
    const float* decay  = (const float*)d_in[3];  // (2, 1)
    float* out          = (float*)d_out;          // (B, E, S)

    krl_fused8<<<Bv * (Ev / TE), THREADS>>>(x, weight, bias, decay, out);
}

// round 9
// speedup vs baseline: 1.2305x; 1.0202x over previous
#include <cuda_runtime.h>
#include <cstdint>

// KernelRepeatLinear: out[b,e,j] = bias[j] + sum_k weight[k,j] * P[b, e-7+k, j]
// P[b,e,j] = sum_{i<=j} x[b,e,i] * dv^(j-i)   (decayed inclusive prefix scan over dim)
#define Bv 8
#define Ev 2048
#define Sv 512
#define Kv 8
#define HALO (Kv - 1)
#define TE 16                 // output E-rows per block
#define ROWS (TE + HALO)      // 23 scanned rows (contiguous in gmem)
#define THREADS 256

// packed fp32x2 FMA (Blackwell)
#define FMA_F32X2(d, a, b, c) \
    asm("fma.rn.f32x2 %0, %1, %2, %3;" : "=l"(d) : "l"(a), "l"(b), "l"(c))

__global__ __launch_bounds__(THREADS, 4)
void krl_fused9(const float* __restrict__ x,
                const float* __restrict__ weight,
                const float* __restrict__ bias,
                const float* __restrict__ decay,
                float* __restrict__ out)
{
    __shared__ float shP[ROWS * Sv];                 // 47104 B tile (x, then P in place)
    __shared__ __align__(8) unsigned long long mbar;

    const int tid  = threadIdx.x;
    const int lane = tid & 31;
    const int warp = tid >> 5;         // 0..7

    const int blocksPerBatch = Ev / TE;           // 128
    const int b  = blockIdx.x / blocksPerBatch;
    const int t  = blockIdx.x % blocksPerBatch;
    const int e0 = t * TE;

    const float* xb = x + (size_t)b * Ev * Sv;

    uint32_t mbar_addr, shP_addr;
    {
        uint64_t tmp;
        asm("cvta.to.shared.u64 %0, %1;" : "=l"(tmp) : "l"(&mbar));
        mbar_addr = (uint32_t)tmp;
        asm("cvta.to.shared.u64 %0, %1;" : "=l"(tmp) : "l"(shP));
        shP_addr = (uint32_t)tmp;
    }

    if (tid == 0)
        asm volatile("mbarrier.init.shared.b64 [%0], %1;" :: "r"(mbar_addr), "r"(1) : "memory");
    __syncthreads();

    const int gFirstWanted = e0 - HALO;
    const int gFirst       = gFirstWanted < 0 ? 0 : gFirstWanted;
    const int dstRow       = gFirst - gFirstWanted;     // 0, or 7 when t==0
    const int nRows        = (e0 + TE) - gFirst;
    const uint32_t bytes   = (uint32_t)nRows * Sv * 4u;

    if (tid == 0) {
        asm volatile("mbarrier.arrive.expect_tx.shared.b64 _, [%0], %1;"
                     :: "r"(mbar_addr), "r"(bytes) : "memory");
        asm volatile("cp.async.bulk.shared::cta.global.mbarrier::complete_tx::bytes "
                     "[%0], [%1], %2, [%3];"
                     :: "r"(shP_addr + (uint32_t)dstRow * Sv * 4u),
                        "l"(xb + (size_t)gFirst * Sv),
                        "r"(bytes), "r"(mbar_addr) : "memory");
    }

    if (dstRow != 0) {                               // zero halo (first tile only)
        float4* z = (float4*)shP;
        for (int i = tid; i < dstRow * (Sv / 4); i += THREADS)
            z[i] = make_float4(0.f, 0.f, 0.f, 0.f);
    }

    float dv = decay[1];
    dv = fminf(1.0f, fmaxf(0.9f, dv));
    const float dv2 = dv * dv;
    const float dv3 = dv2 * dv;
    const float dv4 = dv2 * dv2;
    const float dv8 = dv4 * dv4;
    const float dv16 = dv8 * dv8;

    // hoist weight/bias LDGs: latency hides behind the TMA wait
    const int jq = tid;                               // float2 column, 0..255
    unsigned long long wv[Kv];
    #pragma unroll
    for (int k = 0; k < Kv; ++k)
        wv[k] = ((const unsigned long long*)(weight + k * Sv))[jq];
    const unsigned long long bv = ((const unsigned long long*)bias)[jq];

    // ---- wait for the TMA tile ----
    {
        uint32_t done;
        asm volatile(
            "{\n\t.reg .pred p;\n\t"
            "mbarrier.try_wait.parity.acquire.cta.shared::cta.b64 p, [%1], %2;\n\t"
            "selp.b32 %0, 1, 0, p;\n\t}"
            : "=r"(done) : "r"(mbar_addr), "r"(0) : "memory");
        if (!done) {
            asm volatile(
                "{\n\t.reg .pred P1;\n\t"
                "WAIT_LOOP_%=:\n\t"
                "mbarrier.try_wait.parity.acquire.cta.shared::cta.b64 P1, [%0], %1, 0x989680;\n\t"
                "@P1 bra.uni WAIT_DONE_%=;\n\t"
                "bra.uni WAIT_LOOP_%=;\n\t"
                "WAIT_DONE_%=:\n\t}"
                :: "r"(mbar_addr), "r"(0) : "memory");
        }
    }
    __syncthreads();

    // -------- Phase 1: in-place decayed prefix scan (LDS -> regs -> STS) ------
    for (int r = warp; r < ROWS; r += 8) {
        float4* rowp = (float4*)(shP + r * Sv);
        float4 a[4];
        #pragma unroll
        for (int q = 0; q < 4; ++q) a[q] = rowp[4 * lane + q];

        float p = 0.f;
        #pragma unroll
        for (int q = 0; q < 4; ++q) {
            p = fmaf(dv, p, a[q].x); a[q].x = p;
            p = fmaf(dv, p, a[q].y); a[q].y = p;
            p = fmaf(dv, p, a[q].z); a[q].z = p;
            p = fmaf(dv, p, a[q].w); a[q].w = p;
        }
        float s = p;
        float f = dv16;
        #pragma unroll
        for (int d = 1; d < 32; d <<= 1) {
            float o = __shfl_up_sync(0xffffffffu, s, d);
            if (lane >= d) s = fmaf(f, o, s);
            f = f * f;
        }
        float carry = __shfl_up_sync(0xffffffffu, s, 1);
        if (lane == 0) carry = 0.f;

        float cq = carry * dv;                        // carry * dv^(4q+1)
        #pragma unroll
        for (int q = 0; q < 4; ++q) {
            a[q].x = a[q].x + cq;
            a[q].y = fmaf(cq, dv,  a[q].y);
            a[q].z = fmaf(cq, dv2, a[q].z);
            a[q].w = fmaf(cq, dv3, a[q].w);
            rowp[4 * lane + q] = a[q];
            cq = cq * dv4;
        }
    }
    __syncthreads();

    // -------- Phase 2: scatter-form FIR, 8 INDEPENDENT accumulators ----------
    // out local row o (0..15): acc[o-rb] += w[r-o] * P[row r], r in [o, o+7].
    // Two groups of 8 output rows; scan rows rb..rb+14 feed group rb.
    unsigned long long* outp =
        (unsigned long long*)(out + ((size_t)b * Ev + e0) * Sv);

    #pragma unroll
    for (int g2 = 0; g2 < 2; ++g2) {
        const int rb = g2 * 8;
        unsigned long long acc[8];
        #pragma unroll
        for (int o = 0; o < 8; ++o) acc[o] = bv;

        unsigned long long vcur =
            ((const unsigned long long*)(shP + rb * Sv))[jq];
        #pragma unroll
        for (int i = 0; i < 15; ++i) {
            unsigned long long vnext = 0ull;
            if (i < 14)
                vnext = ((const unsigned long long*)(shP + (rb + i + 1) * Sv))[jq];
            // scan row rb+i contributes w[k] to acc[i-k] for k in [i-7, i] & [0,7]
            #pragma unroll
            for (int k = 0; k < 8; ++k) {
                if (i - k >= 0 && i - k < 8)
                    FMA_F32X2(acc[i - k], wv[k], vcur, acc[i - k]);
            }
            vcur = vnext;
        }
        #pragma unroll
        for (int o = 0; o < 8; ++o)
            outp[(size_t)(rb + o) * (Sv / 2) + jq] = acc[o];
    }
}

extern "C" void kernel_launch(void* const* d_in, const int* in_sizes, int n_in,
                              void* d_out, int out_size)
{
    const float* x      = (const float*)d_in[0];  // (B, E, S)
    const float* weight = (const float*)d_in[1];  // (K, S)
    const float* bias   = (const float*)d_in[2];  // (S,)
    const float* decay  = (const float*)d_in[3];  // (2, 1)
    float* out          = (float*)d_out;          // (B, E, S)

    krl_fused9<<<Bv * (Ev / TE), THREADS>>>(x, weight, bias, decay, out);
}